// round 8
// baseline (speedup 1.0000x reference)
#include <cuda_runtime.h>
#include <cuda_fp16.h>
#include <math.h>
#include <stdint.h>

#define N_NODES   50000
#define N_EDGES   800000
#define TOT_EDGES (N_EDGES + N_NODES)
#define HEADS     4
#define OUT_CH    64
#define DHID      256
#define KDIM      256
#define NBLK      196        // ceil(N_NODES/256)

#define MSPLIT_BLK 196                   // gemm blocks in part a
#define NODE_SPLIT (MSPLIT_BLK * 128)    // 25088

// ---------------- scratch (static device globals; no allocation) ------------
__device__ __half g_h_half[N_NODES * DHID];
__device__ __half g_act[N_NODES * DHID];
__device__ __half g_x_half[N_NODES * KDIM];
__device__ __half g_w1t[DHID * KDIM];
__device__ __half g_w2t[DHID * KDIM];
__device__ float  g_asrc[N_NODES * HEADS];
__device__ float  g_adst[N_NODES * HEADS];
__device__ int    g_deg[N_NODES];
__device__ int    g_rowptr[N_NODES + 1];
__device__ int    g_cursor[N_NODES];
__device__ int    g_csr_src[TOT_EDGES];
__device__ int    g_blocksums[256];

// ---------------- streams/events (created at load time) ---------------------
struct GraphStreams {
    cudaStream_t s2 = nullptr;
    cudaEvent_t ev0 = nullptr, evX = nullptr, evG1 = nullptr;
    cudaEvent_t evA1a = nullptr, evG2a = nullptr;
    GraphStreams() {
        cudaStreamCreateWithFlags(&s2, cudaStreamNonBlocking);
        cudaEventCreateWithFlags(&ev0, cudaEventDisableTiming);
        cudaEventCreateWithFlags(&evX, cudaEventDisableTiming);
        cudaEventCreateWithFlags(&evG1, cudaEventDisableTiming);
        cudaEventCreateWithFlags(&evA1a, cudaEventDisableTiming);
        cudaEventCreateWithFlags(&evG2a, cudaEventDisableTiming);
    }
};
static GraphStreams g_gs;

__device__ __forceinline__ void cp_async16(uint32_t smem_dst, const void* gsrc, int src_bytes) {
    asm volatile("cp.async.cg.shared.global [%0], [%1], 16, %2;"
                 :: "r"(smem_dst), "l"(gsrc), "r"(src_bytes));
}

// ========================= input conversion (+ deg zero) =====================
__global__ void convert_x_kernel(const float* __restrict__ x) {
    int i = blockIdx.x * blockDim.x + threadIdx.x;
    const int TOT8 = N_NODES * KDIM / 8;
    if (i < N_NODES) g_deg[i] = 0;           // fused zero_deg
    if (i >= TOT8) return;
    float4 v0 = ((const float4*)x)[2 * i];
    float4 v1 = ((const float4*)x)[2 * i + 1];
    __half2 h0 = __floats2half2_rn(v0.x, v0.y);
    __half2 h1 = __floats2half2_rn(v0.z, v0.w);
    __half2 h2 = __floats2half2_rn(v1.x, v1.y);
    __half2 h3 = __floats2half2_rn(v1.z, v1.w);
    uint4 packed = make_uint4(*(uint32_t*)&h0, *(uint32_t*)&h1,
                              *(uint32_t*)&h2, *(uint32_t*)&h3);
    ((uint4*)g_x_half)[i] = packed;
}

__global__ void convert_w_kernel(const float* __restrict__ W1,
                                 const float* __restrict__ W2) {
    const float* W = blockIdx.z ? W2 : W1;
    __half* Wt = blockIdx.z ? g_w2t : g_w1t;
    __shared__ float tile[32][33];
    int bx = blockIdx.x * 32, by = blockIdx.y * 32;
    int tx = threadIdx.x, ty = threadIdx.y;   // block (32, 8)
    #pragma unroll
    for (int i = 0; i < 32; i += 8)
        tile[ty + i][tx] = W[(by + ty + i) * DHID + bx + tx];
    __syncthreads();
    #pragma unroll
    for (int i = 0; i < 32; i += 8)
        Wt[(bx + ty + i) * KDIM + by + tx] = __float2half(tile[tx][ty + i]);
}

// ========================= CSR build =========================
__global__ void count_kernel(const int* __restrict__ ei) {
    int i = blockIdx.x * blockDim.x + threadIdx.x;
    if (i >= TOT_EDGES) return;
    int d = (i < N_EDGES) ? ei[N_EDGES + i] : (i - N_EDGES);
    atomicAdd(&g_deg[d], 1);
}

__global__ void block_reduce_kernel() {
    __shared__ int sh[256];
    int t = threadIdx.x;
    int i = blockIdx.x * 256 + t;
    sh[t] = (i < N_NODES) ? g_deg[i] : 0;
    __syncthreads();
    for (int o = 128; o > 0; o >>= 1) {
        if (t < o) sh[t] += sh[t + o];
        __syncthreads();
    }
    if (t == 0) g_blocksums[blockIdx.x] = sh[0];
}

__global__ void scan_blocks_kernel() {
    __shared__ int sh[256];
    int t = threadIdx.x;
    int v = (t < NBLK) ? g_blocksums[t] : 0;
    sh[t] = v;
    __syncthreads();
    for (int o = 1; o < 256; o <<= 1) {
        int x = (t >= o) ? sh[t - o] : 0;
        __syncthreads();
        sh[t] += x;
        __syncthreads();
    }
    if (t < NBLK) g_blocksums[t] = sh[t] - v;
}

__global__ void scatter_rowptr_kernel() {
    __shared__ int sh[256];
    int t = threadIdx.x;
    int i = blockIdx.x * 256 + t;
    int v = (i < N_NODES) ? g_deg[i] : 0;
    sh[t] = v;
    __syncthreads();
    for (int o = 1; o < 256; o <<= 1) {
        int x = (t >= o) ? sh[t - o] : 0;
        __syncthreads();
        sh[t] += x;
        __syncthreads();
    }
    int off = g_blocksums[blockIdx.x];
    if (i < N_NODES) {
        int r = off + sh[t] - v;
        g_rowptr[i] = r;
        g_cursor[i] = r;
        if (i == N_NODES - 1) g_rowptr[N_NODES] = TOT_EDGES;
    }
}

__global__ void fill_kernel(const int* __restrict__ ei) {
    int i = blockIdx.x * blockDim.x + threadIdx.x;
    if (i >= TOT_EDGES) return;
    int s, d;
    if (i < N_EDGES) { s = ei[i]; d = ei[N_EDGES + i]; }
    else             { s = d = i - N_EDGES; }
    int pos = atomicAdd(&g_cursor[d], 1);
    g_csr_src[pos] = s;
}

// ========================= fp16 GEMM + fused attn + fp16 store ===============
// mbase: M-block offset (for split launches)
#define BM 128
#define BN 128
#define BK 32
#define STRH 40

__global__ __launch_bounds__(256) void gemm_f16_kernel(
    int layer, int mbase,
    const float* __restrict__ att_src, const float* __restrict__ att_dst)
{
    const __half* A  = layer ? (const __half*)g_act : (const __half*)g_x_half;
    const __half* Bt = layer ? (const __half*)g_w2t : (const __half*)g_w1t;

    __shared__ __half As[2][BM][STRH];
    __shared__ __half Bs[2][BN][STRH];
    float* s_attn = (float*)As;

    int bm = (mbase + blockIdx.x) * BM;
    int bn = blockIdx.y * BN;
    int tid  = threadIdx.x;
    int warp = tid >> 5;
    int lane = tid & 31;
    int wm = (warp & 1) * 64;
    int wn = (warp >> 1) * 32;
    int lr = lane >> 2;
    int lc = lane & 3;

    float c[4][4][4];
    #pragma unroll
    for (int mt = 0; mt < 4; mt++)
        #pragma unroll
        for (int nt = 0; nt < 4; nt++)
            #pragma unroll
            for (int f = 0; f < 4; f++) c[mt][nt][f] = 0.f;

    auto load_tiles = [&](int st, int k0) {
        #pragma unroll
        for (int i = 0; i < 2; i++) {
            int idx = tid + i * 256;
            int r = idx >> 2;
            int cg = (idx & 3) * 8;
            int gr = bm + r;
            int valid = (gr < N_NODES);
            int src_row = valid ? gr : 0;
            uint32_t dst = (uint32_t)__cvta_generic_to_shared(&As[st][r][cg]);
            cp_async16(dst, &A[(long)src_row * KDIM + k0 + cg], valid ? 16 : 0);
        }
        #pragma unroll
        for (int i = 0; i < 2; i++) {
            int idx = tid + i * 256;
            int r = idx >> 2;
            int cg = (idx & 3) * 8;
            uint32_t dst = (uint32_t)__cvta_generic_to_shared(&Bs[st][r][cg]);
            cp_async16(dst, &Bt[(long)(bn + r) * KDIM + k0 + cg], 16);
        }
        asm volatile("cp.async.commit_group;");
    };

    load_tiles(0, 0);

    const int NITER = KDIM / BK;   // 8
    #pragma unroll 1
    for (int it = 0; it < NITER; it++) {
        if (it + 1 < NITER) load_tiles((it + 1) & 1, (it + 1) * BK);
        if (it + 1 < NITER) asm volatile("cp.async.wait_group 1;");
        else                asm volatile("cp.async.wait_group 0;");
        __syncthreads();
        int st = it & 1;

        #pragma unroll
        for (int ks = 0; ks < 2; ks++) {
            int k = ks * 16;
            uint32_t af[4][4];
            #pragma unroll
            for (int mt = 0; mt < 4; mt++) {
                int r0 = wm + mt * 16 + lr;
                af[mt][0] = *(const uint32_t*)&As[st][r0][k + 2 * lc];
                af[mt][1] = *(const uint32_t*)&As[st][r0 + 8][k + 2 * lc];
                af[mt][2] = *(const uint32_t*)&As[st][r0][k + 2 * lc + 8];
                af[mt][3] = *(const uint32_t*)&As[st][r0 + 8][k + 2 * lc + 8];
            }
            uint32_t bf[4][2];
            #pragma unroll
            for (int nt = 0; nt < 4; nt++) {
                int col = wn + nt * 8 + lr;
                bf[nt][0] = *(const uint32_t*)&Bs[st][col][k + 2 * lc];
                bf[nt][1] = *(const uint32_t*)&Bs[st][col][k + 2 * lc + 8];
            }
            #pragma unroll
            for (int mt = 0; mt < 4; mt++)
                #pragma unroll
                for (int nt = 0; nt < 4; nt++) {
                    asm volatile(
                        "mma.sync.aligned.m16n8k16.row.col.f32.f16.f16.f32 "
                        "{%0,%1,%2,%3}, {%4,%5,%6,%7}, {%8,%9}, {%0,%1,%2,%3};"
                        : "+f"(c[mt][nt][0]), "+f"(c[mt][nt][1]),
                          "+f"(c[mt][nt][2]), "+f"(c[mt][nt][3])
                        : "r"(af[mt][0]), "r"(af[mt][1]), "r"(af[mt][2]), "r"(af[mt][3]),
                          "r"(bf[nt][0]), "r"(bf[nt][1]));
                }
        }
        __syncthreads();
    }

    // ---- store C as fp16 ----
    #pragma unroll
    for (int mt = 0; mt < 4; mt++) {
        int row0 = bm + wm + mt * 16 + lr;
        #pragma unroll
        for (int nt = 0; nt < 4; nt++) {
            int col = bn + wn + nt * 8 + 2 * lc;
            if (row0 < N_NODES)
                *(__half2*)&g_h_half[(long)row0 * DHID + col] =
                    __floats2half2_rn(c[mt][nt][0], c[mt][nt][1]);
            if (row0 + 8 < N_NODES)
                *(__half2*)&g_h_half[(long)(row0 + 8) * DHID + col] =
                    __floats2half2_rn(c[mt][nt][2], c[mt][nt][3]);
        }
    }

    // ---- fused attention scores (block owns heads 2*by, 2*by+1) ----
    int head_l = wn >> 6;
    int slot   = (wn >> 5) & 1;
    float attS[4][2], attD[4][2];
    #pragma unroll
    for (int nt = 0; nt < 4; nt++)
        #pragma unroll
        for (int j = 0; j < 2; j++) {
            int col = bn + wn + nt * 8 + 2 * lc + j;
            attS[nt][j] = att_src[col];
            attD[nt][j] = att_dst[col];
        }
    __syncthreads();
    #pragma unroll
    for (int mt = 0; mt < 4; mt++) {
        float s0 = 0.f, d0 = 0.f, s1 = 0.f, d1 = 0.f;
        #pragma unroll
        for (int nt = 0; nt < 4; nt++) {
            s0 += c[mt][nt][0] * attS[nt][0] + c[mt][nt][1] * attS[nt][1];
            d0 += c[mt][nt][0] * attD[nt][0] + c[mt][nt][1] * attD[nt][1];
            s1 += c[mt][nt][2] * attS[nt][0] + c[mt][nt][3] * attS[nt][1];
            d1 += c[mt][nt][2] * attD[nt][0] + c[mt][nt][3] * attD[nt][1];
        }
        #pragma unroll
        for (int o = 1; o < 4; o <<= 1) {
            s0 += __shfl_xor_sync(0xFFFFFFFFu, s0, o);
            d0 += __shfl_xor_sync(0xFFFFFFFFu, d0, o);
            s1 += __shfl_xor_sync(0xFFFFFFFFu, s1, o);
            d1 += __shfl_xor_sync(0xFFFFFFFFu, d1, o);
        }
        if (lc == 0) {
            int r0 = wm + mt * 16 + lr;
            s_attn[((0 * 2 + head_l) * 2 + slot) * BM + r0]     = s0;
            s_attn[((1 * 2 + head_l) * 2 + slot) * BM + r0]     = d0;
            s_attn[((0 * 2 + head_l) * 2 + slot) * BM + r0 + 8] = s1;
            s_attn[((1 * 2 + head_l) * 2 + slot) * BM + r0 + 8] = d1;
        }
    }
    __syncthreads();
    {
        int row = tid & 127;
        int hl  = tid >> 7;
        int node = bm + row;
        if (node < N_NODES) {
            int hg = blockIdx.y * 2 + hl;
            g_asrc[node * 4 + hg] = s_attn[((0 * 2 + hl) * 2 + 0) * BM + row]
                                  + s_attn[((0 * 2 + hl) * 2 + 1) * BM + row];
            g_adst[node * 4 + hg] = s_attn[((1 * 2 + hl) * 2 + 0) * BM + row]
                                  + s_attn[((1 * 2 + hl) * 2 + 1) * BM + row];
        }
    }
}

// ========================= fused aggregate (warp per node, [n0,n1)) ==========
__device__ __forceinline__ float4 eexp4(float4 a, float4 b) {
    float4 e;
    e.x = a.x + b.x; e.y = a.y + b.y; e.z = a.z + b.z; e.w = a.w + b.w;
    e.x = (e.x > 0.f) ? e.x : 0.2f * e.x;
    e.y = (e.y > 0.f) ? e.y : 0.2f * e.y;
    e.z = (e.z > 0.f) ? e.z : 0.2f * e.z;
    e.w = (e.w > 0.f) ? e.w : 0.2f * e.w;
    e.x = __expf(e.x); e.y = __expf(e.y); e.z = __expf(e.z); e.w = __expf(e.w);
    return e;
}

__device__ __forceinline__ void fma8(float* acc, float alpha, uint4 raw) {
    float2 f0 = __half22float2(*(__half2*)&raw.x);
    float2 f1 = __half22float2(*(__half2*)&raw.y);
    float2 f2 = __half22float2(*(__half2*)&raw.z);
    float2 f3 = __half22float2(*(__half2*)&raw.w);
    acc[0] += alpha * f0.x; acc[1] += alpha * f0.y;
    acc[2] += alpha * f1.x; acc[3] += alpha * f1.y;
    acc[4] += alpha * f2.x; acc[5] += alpha * f2.y;
    acc[6] += alpha * f3.x; acc[7] += alpha * f3.y;
}

__global__ __launch_bounds__(256) void gat_aggregate_kernel(
    const float* __restrict__ bias, float* __restrict__ dst_ext, int to_act,
    int n0, int n1)
{
    int n    = n0 + ((blockIdx.x * blockDim.x + threadIdx.x) >> 5);
    int lane = threadIdx.x & 31;
    if (n >= n1) return;
    int beg = g_rowptr[n];
    int end = g_rowptr[n + 1];
    float4 adst = *(const float4*)&g_adst[n * 4];

    // pass 1: denominator
    float4 dsum = make_float4(0.f, 0.f, 0.f, 0.f);
    for (int e = beg + lane; e < end; e += 32) {
        int s = g_csr_src[e];
        float4 a = *(const float4*)&g_asrc[s * 4];
        float4 ee = eexp4(a, adst);
        dsum.x += ee.x; dsum.y += ee.y; dsum.z += ee.z; dsum.w += ee.w;
    }
    #pragma unroll
    for (int o = 16; o > 0; o >>= 1) {
        dsum.x += __shfl_xor_sync(0xFFFFFFFFu, dsum.x, o);
        dsum.y += __shfl_xor_sync(0xFFFFFFFFu, dsum.y, o);
        dsum.z += __shfl_xor_sync(0xFFFFFFFFu, dsum.z, o);
        dsum.w += __shfl_xor_sync(0xFFFFFFFFu, dsum.w, o);
    }
    int head = lane >> 3;
    float den = (head == 0) ? dsum.x : (head == 1) ? dsum.y : (head == 2) ? dsum.z : dsum.w;
    float inv = 1.f / (den + 1e-16f);
    float adst_h = (head == 0) ? adst.x : (head == 1) ? adst.y : (head == 2) ? adst.z : adst.w;

    // pass 2: scalar per-head score, unrolled x4
    float acc[8] = {0.f, 0.f, 0.f, 0.f, 0.f, 0.f, 0.f, 0.f};
    int e = beg;
    for (; e + 4 <= end; e += 4) {
        int i0 = g_csr_src[e];
        int i1 = g_csr_src[e + 1];
        int i2 = g_csr_src[e + 2];
        int i3 = g_csr_src[e + 3];
        float a0 = __ldg(&g_asrc[i0 * 4 + head]);
        float a1 = __ldg(&g_asrc[i1 * 4 + head]);
        float a2 = __ldg(&g_asrc[i2 * 4 + head]);
        float a3 = __ldg(&g_asrc[i3 * 4 + head]);
        uint4 r0 = *(const uint4*)&g_h_half[(long)i0 * DHID + lane * 8];
        uint4 r1 = *(const uint4*)&g_h_half[(long)i1 * DHID + lane * 8];
        uint4 r2 = *(const uint4*)&g_h_half[(long)i2 * DHID + lane * 8];
        uint4 r3 = *(const uint4*)&g_h_half[(long)i3 * DHID + lane * 8];
        float e0 = a0 + adst_h; e0 = (e0 > 0.f) ? e0 : 0.2f * e0;
        float e1 = a1 + adst_h; e1 = (e1 > 0.f) ? e1 : 0.2f * e1;
        float e2 = a2 + adst_h; e2 = (e2 > 0.f) ? e2 : 0.2f * e2;
        float e3 = a3 + adst_h; e3 = (e3 > 0.f) ? e3 : 0.2f * e3;
        fma8(acc, __expf(e0) * inv, r0);
        fma8(acc, __expf(e1) * inv, r1);
        fma8(acc, __expf(e2) * inv, r2);
        fma8(acc, __expf(e3) * inv, r3);
    }
    for (; e < end; e++) {
        int i0 = g_csr_src[e];
        float a0 = __ldg(&g_asrc[i0 * 4 + head]);
        uint4 r0 = *(const uint4*)&g_h_half[(long)i0 * DHID + lane * 8];
        float e0 = a0 + adst_h; e0 = (e0 > 0.f) ? e0 : 0.2f * e0;
        fma8(acc, __expf(e0) * inv, r0);
    }

    // epilogue: bias + ELU + store
    float4 b0 = ((const float4*)bias)[lane * 2];
    float4 b1 = ((const float4*)bias)[lane * 2 + 1];
    float bb[8] = {b0.x, b0.y, b0.z, b0.w, b1.x, b1.y, b1.z, b1.w};
    #pragma unroll
    for (int i = 0; i < 8; i++) {
        float v = acc[i] + bb[i];
        acc[i] = (v > 0.f) ? v : expm1f(v);
    }
    if (to_act) {
        __half2 h0 = __floats2half2_rn(acc[0], acc[1]);
        __half2 h1 = __floats2half2_rn(acc[2], acc[3]);
        __half2 h2 = __floats2half2_rn(acc[4], acc[5]);
        __half2 h3 = __floats2half2_rn(acc[6], acc[7]);
        uint4 packed = make_uint4(*(uint32_t*)&h0, *(uint32_t*)&h1,
                                  *(uint32_t*)&h2, *(uint32_t*)&h3);
        *(uint4*)&g_act[(long)n * DHID + lane * 8] = packed;
    } else {
        float* op = &dst_ext[(long)n * DHID + lane * 8];
        *(float4*)op       = make_float4(acc[0], acc[1], acc[2], acc[3]);
        *(float4*)(op + 4) = make_float4(acc[4], acc[5], acc[6], acc[7]);
    }
}

// ========================= launch =========================
extern "C" void kernel_launch(void* const* d_in, const int* in_sizes, int n_in,
                              void* d_out, int out_size)
{
    const float* x   = (const float*)d_in[0];
    const int*   ei  = (const int*)  d_in[1];
    const float* W1  = (const float*)d_in[2];
    const float* as1 = (const float*)d_in[3];
    const float* ad1 = (const float*)d_in[4];
    const float* b1  = (const float*)d_in[5];
    const float* W2  = (const float*)d_in[6];
    const float* as2 = (const float*)d_in[7];
    const float* ad2 = (const float*)d_in[8];
    const float* b2  = (const float*)d_in[9];
    float* out = (float*)d_out;

    cudaStream_t s0 = 0;           // legacy default (captured stream)
    cudaStream_t s2 = g_gs.s2;

    int gemm_mblocks = (N_NODES + BM - 1) / BM;      // 391
    dim3 gemm_grid_full(gemm_mblocks, DHID / BN);
    dim3 gemm_grid_a(MSPLIT_BLK, DHID / BN);                     // rows [0, 25088)
    dim3 gemm_grid_b(gemm_mblocks - MSPLIT_BLK, DHID / BN);      // rows [25088, ...)
    int edge_blocks = (TOT_EDGES + 255) / 256;
    int agg_blocks_full = (N_NODES + 7) / 8;
    int agg_blocks_a = (NODE_SPLIT + 7) / 8;                     // 3136
    int agg_blocks_b = (N_NODES - NODE_SPLIT + 7) / 8;           // 3114
    int cvtx_blocks = (N_NODES * KDIM / 8 + 255) / 256;
    dim3 wgrid(8, 8, 2), wblk(32, 8);

    // fork point
    cudaEventRecord(g_gs.ev0, s0);
    cudaStreamWaitEvent(s2, g_gs.ev0, 0);

    // ---- s0: convert x (+zero deg), then CSR build ----
    convert_x_kernel<<<cvtx_blocks, 256, 0, s0>>>(x);
    cudaEventRecord(g_gs.evX, s0);
    count_kernel<<<edge_blocks, 256, 0, s0>>>(ei);
    block_reduce_kernel<<<NBLK, 256, 0, s0>>>();
    scan_blocks_kernel<<<1, 256, 0, s0>>>();
    scatter_rowptr_kernel<<<NBLK, 256, 0, s0>>>();
    fill_kernel<<<edge_blocks, 256, 0, s0>>>(ei);

    // ---- s2: weights + layer-1 GEMM (needs x conversion) ----
    convert_w_kernel<<<wgrid, wblk, 0, s2>>>(W1, W2);
    cudaStreamWaitEvent(s2, g_gs.evX, 0);
    gemm_f16_kernel<<<gemm_grid_full, 256, 0, s2>>>(0, 0, as1, ad1);
    cudaEventRecord(g_gs.evG1, s2);

    // ---- layer-1 aggregate, split-pipelined with layer-2 GEMM ----
    cudaStreamWaitEvent(s0, g_gs.evG1, 0);
    gat_aggregate_kernel<<<agg_blocks_a, 256, 0, s0>>>(b1, nullptr, 1, 0, NODE_SPLIT);
    cudaEventRecord(g_gs.evA1a, s0);
    gat_aggregate_kernel<<<agg_blocks_b, 256, 0, s0>>>(b1, nullptr, 1, NODE_SPLIT, N_NODES);

    // s2: gemm2 over rows [0, NODE_SPLIT) concurrently with agg1b
    cudaStreamWaitEvent(s2, g_gs.evA1a, 0);
    gemm_f16_kernel<<<gemm_grid_a, 256, 0, s2>>>(1, 0, as2, ad2);
    cudaEventRecord(g_gs.evG2a, s2);

    // s0: gemm2 over remaining rows (after agg1b, program order)
    gemm_f16_kernel<<<gemm_grid_b, 256, 0, s0>>>(1, MSPLIT_BLK, as2, ad2);
    cudaStreamWaitEvent(s0, g_gs.evG2a, 0);

    // ---- layer-2 aggregate -> output ----
    gat_aggregate_kernel<<<agg_blocks_full, 256, 0, s0>>>(b2, out, 0, 0, N_NODES);
}

// round 9
// speedup vs baseline: 1.0336x; 1.0336x over previous
#include <cuda_runtime.h>
#include <cuda_fp16.h>
#include <math.h>
#include <stdint.h>

#define N_NODES   50000
#define N_EDGES   800000
#define TOT_EDGES (N_EDGES + N_NODES)
#define HEADS     4
#define OUT_CH    64
#define DHID      256
#define KDIM      256
#define NBLK      196        // ceil(N_NODES/256)

// ---------------- scratch (static device globals; no allocation) ------------
__device__ __half g_h_half[N_NODES * DHID];
__device__ __half g_act[N_NODES * DHID];
__device__ __half g_x_half[N_NODES * KDIM];
__device__ __half g_w1t[DHID * KDIM];
__device__ __half g_w2t[DHID * KDIM];
__device__ float  g_asrc[N_NODES * HEADS];
__device__ float  g_adst[N_NODES * HEADS];
__device__ int    g_deg[N_NODES];
__device__ int    g_rowptr[N_NODES + 1];
__device__ int    g_cursor[N_NODES];
__device__ int    g_csr_src[TOT_EDGES];
__device__ int    g_blocksums[256];

// ---------------- streams/events (created at load time) ---------------------
struct GraphStreams {
    cudaStream_t s2 = nullptr;
    cudaEvent_t ev0 = nullptr, evX = nullptr, evG1 = nullptr;
    GraphStreams() {
        cudaStreamCreateWithFlags(&s2, cudaStreamNonBlocking);
        cudaEventCreateWithFlags(&ev0, cudaEventDisableTiming);
        cudaEventCreateWithFlags(&evX, cudaEventDisableTiming);
        cudaEventCreateWithFlags(&evG1, cudaEventDisableTiming);
    }
};
static GraphStreams g_gs;

__device__ __forceinline__ void cp_async16(uint32_t smem_dst, const void* gsrc, int src_bytes) {
    asm volatile("cp.async.cg.shared.global [%0], [%1], 16, %2;"
                 :: "r"(smem_dst), "l"(gsrc), "r"(src_bytes));
}

__device__ __forceinline__ void ldsm_x4(uint32_t& r0, uint32_t& r1,
                                        uint32_t& r2, uint32_t& r3,
                                        const void* smem_ptr) {
    uint32_t addr = (uint32_t)__cvta_generic_to_shared(smem_ptr);
    asm volatile("ldmatrix.sync.aligned.m8n8.x4.shared.b16 {%0,%1,%2,%3}, [%4];"
                 : "=r"(r0), "=r"(r1), "=r"(r2), "=r"(r3) : "r"(addr));
}

// ========================= input conversion (+ deg zero) =====================
__global__ void convert_x_kernel(const float* __restrict__ x) {
    int i = blockIdx.x * blockDim.x + threadIdx.x;
    const int TOT8 = N_NODES * KDIM / 8;
    if (i < N_NODES) g_deg[i] = 0;           // fused zero_deg
    if (i >= TOT8) return;
    float4 v0 = ((const float4*)x)[2 * i];
    float4 v1 = ((const float4*)x)[2 * i + 1];
    __half2 h0 = __floats2half2_rn(v0.x, v0.y);
    __half2 h1 = __floats2half2_rn(v0.z, v0.w);
    __half2 h2 = __floats2half2_rn(v1.x, v1.y);
    __half2 h3 = __floats2half2_rn(v1.z, v1.w);
    uint4 packed = make_uint4(*(uint32_t*)&h0, *(uint32_t*)&h1,
                              *(uint32_t*)&h2, *(uint32_t*)&h3);
    ((uint4*)g_x_half)[i] = packed;
}

__global__ void convert_w_kernel(const float* __restrict__ W1,
                                 const float* __restrict__ W2) {
    const float* W = blockIdx.z ? W2 : W1;
    __half* Wt = blockIdx.z ? g_w2t : g_w1t;
    __shared__ float tile[32][33];
    int bx = blockIdx.x * 32, by = blockIdx.y * 32;
    int tx = threadIdx.x, ty = threadIdx.y;   // block (32, 8)
    #pragma unroll
    for (int i = 0; i < 32; i += 8)
        tile[ty + i][tx] = W[(by + ty + i) * DHID + bx + tx];
    __syncthreads();
    #pragma unroll
    for (int i = 0; i < 32; i += 8)
        Wt[(bx + ty + i) * KDIM + by + tx] = __float2half(tile[tx][ty + i]);
}

// ========================= CSR build =========================
__global__ void count_kernel(const int* __restrict__ ei) {
    int i = blockIdx.x * blockDim.x + threadIdx.x;
    if (i >= TOT_EDGES) return;
    int d = (i < N_EDGES) ? ei[N_EDGES + i] : (i - N_EDGES);
    atomicAdd(&g_deg[d], 1);
}

__global__ void block_reduce_kernel() {
    __shared__ int sh[256];
    int t = threadIdx.x;
    int i = blockIdx.x * 256 + t;
    sh[t] = (i < N_NODES) ? g_deg[i] : 0;
    __syncthreads();
    for (int o = 128; o > 0; o >>= 1) {
        if (t < o) sh[t] += sh[t + o];
        __syncthreads();
    }
    if (t == 0) g_blocksums[blockIdx.x] = sh[0];
}

__global__ void scan_blocks_kernel() {
    __shared__ int sh[256];
    int t = threadIdx.x;
    int v = (t < NBLK) ? g_blocksums[t] : 0;
    sh[t] = v;
    __syncthreads();
    for (int o = 1; o < 256; o <<= 1) {
        int x = (t >= o) ? sh[t - o] : 0;
        __syncthreads();
        sh[t] += x;
        __syncthreads();
    }
    if (t < NBLK) g_blocksums[t] = sh[t] - v;
}

__global__ void scatter_rowptr_kernel() {
    __shared__ int sh[256];
    int t = threadIdx.x;
    int i = blockIdx.x * 256 + t;
    int v = (i < N_NODES) ? g_deg[i] : 0;
    sh[t] = v;
    __syncthreads();
    for (int o = 1; o < 256; o <<= 1) {
        int x = (t >= o) ? sh[t - o] : 0;
        __syncthreads();
        sh[t] += x;
        __syncthreads();
    }
    int off = g_blocksums[blockIdx.x];
    if (i < N_NODES) {
        int r = off + sh[t] - v;
        g_rowptr[i] = r;
        g_cursor[i] = r;
        if (i == N_NODES - 1) g_rowptr[N_NODES] = TOT_EDGES;
    }
}

__global__ void fill_kernel(const int* __restrict__ ei) {
    int i = blockIdx.x * blockDim.x + threadIdx.x;
    if (i >= TOT_EDGES) return;
    int s, d;
    if (i < N_EDGES) { s = ei[i]; d = ei[N_EDGES + i]; }
    else             { s = d = i - N_EDGES; }
    int pos = atomicAdd(&g_cursor[d], 1);
    g_csr_src[pos] = s;
}

// ========================= fp16 GEMM + fused attn + fp16 store ===============
#define BM 128
#define BN 128
#define BK 32
#define STRH 40

__global__ __launch_bounds__(256) void gemm_f16_kernel(
    int layer,
    const float* __restrict__ att_src, const float* __restrict__ att_dst)
{
    const __half* A  = layer ? (const __half*)g_act : (const __half*)g_x_half;
    const __half* Bt = layer ? (const __half*)g_w2t : (const __half*)g_w1t;

    __shared__ __half As[2][BM][STRH];
    __shared__ __half Bs[2][BN][STRH];
    float* s_attn = (float*)As;

    int bm = blockIdx.x * BM;
    int bn = blockIdx.y * BN;
    int tid  = threadIdx.x;
    int warp = tid >> 5;
    int lane = tid & 31;
    int wm = (warp & 1) * 64;
    int wn = (warp >> 1) * 32;
    int lr = lane >> 2;
    int lc = lane & 3;
    int lg = lane >> 3;     // ldmatrix group 0..3
    int rl = lane & 7;      // row within group

    float c[4][4][4];
    #pragma unroll
    for (int mt = 0; mt < 4; mt++)
        #pragma unroll
        for (int nt = 0; nt < 4; nt++)
            #pragma unroll
            for (int f = 0; f < 4; f++) c[mt][nt][f] = 0.f;

    auto load_tiles = [&](int st, int k0) {
        #pragma unroll
        for (int i = 0; i < 2; i++) {
            int idx = tid + i * 256;
            int r = idx >> 2;
            int cg = (idx & 3) * 8;
            int gr = bm + r;
            int valid = (gr < N_NODES);
            int src_row = valid ? gr : 0;
            uint32_t dst = (uint32_t)__cvta_generic_to_shared(&As[st][r][cg]);
            cp_async16(dst, &A[(long)src_row * KDIM + k0 + cg], valid ? 16 : 0);
        }
        #pragma unroll
        for (int i = 0; i < 2; i++) {
            int idx = tid + i * 256;
            int r = idx >> 2;
            int cg = (idx & 3) * 8;
            uint32_t dst = (uint32_t)__cvta_generic_to_shared(&Bs[st][r][cg]);
            cp_async16(dst, &Bt[(long)(bn + r) * KDIM + k0 + cg], 16);
        }
        asm volatile("cp.async.commit_group;");
    };

    load_tiles(0, 0);

    const int NITER = KDIM / BK;   // 8
    #pragma unroll 1
    for (int it = 0; it < NITER; it++) {
        if (it + 1 < NITER) load_tiles((it + 1) & 1, (it + 1) * BK);
        if (it + 1 < NITER) asm volatile("cp.async.wait_group 1;");
        else                asm volatile("cp.async.wait_group 0;");
        __syncthreads();
        int st = it & 1;

        #pragma unroll
        for (int ks = 0; ks < 2; ks++) {
            int k = ks * 16;
            // A fragments via ldmatrix x4: matrices = {rows0-7 k0-7, rows8-15 k0-7,
            //                                          rows0-7 k8-15, rows8-15 k8-15}
            uint32_t af[4][4];
            #pragma unroll
            for (int mt = 0; mt < 4; mt++) {
                const __half* p = &As[st][wm + mt * 16 + ((lg & 1) << 3) + rl]
                                        [k + ((lg >> 1) << 3)];
                ldsm_x4(af[mt][0], af[mt][1], af[mt][2], af[mt][3], p);
            }
            // B fragments via ldmatrix x4: two nt tiles per instruction
            // matrices = {nt0 k0-7, nt0 k8-15, nt1 k0-7, nt1 k8-15}
            uint32_t bf[4][2];
            #pragma unroll
            for (int p2 = 0; p2 < 2; p2++) {
                int ntb = p2 * 2 + (lg >> 1);
                const __half* p = &Bs[st][wn + ntb * 8 + rl][k + ((lg & 1) << 3)];
                ldsm_x4(bf[p2 * 2][0], bf[p2 * 2][1],
                        bf[p2 * 2 + 1][0], bf[p2 * 2 + 1][1], p);
            }
            #pragma unroll
            for (int mt = 0; mt < 4; mt++)
                #pragma unroll
                for (int nt = 0; nt < 4; nt++) {
                    asm volatile(
                        "mma.sync.aligned.m16n8k16.row.col.f32.f16.f16.f32 "
                        "{%0,%1,%2,%3}, {%4,%5,%6,%7}, {%8,%9}, {%0,%1,%2,%3};"
                        : "+f"(c[mt][nt][0]), "+f"(c[mt][nt][1]),
                          "+f"(c[mt][nt][2]), "+f"(c[mt][nt][3])
                        : "r"(af[mt][0]), "r"(af[mt][1]), "r"(af[mt][2]), "r"(af[mt][3]),
                          "r"(bf[nt][0]), "r"(bf[nt][1]));
                }
        }
        __syncthreads();
    }

    // ---- store C as fp16 ----
    #pragma unroll
    for (int mt = 0; mt < 4; mt++) {
        int row0 = bm + wm + mt * 16 + lr;
        #pragma unroll
        for (int nt = 0; nt < 4; nt++) {
            int col = bn + wn + nt * 8 + 2 * lc;
            if (row0 < N_NODES)
                *(__half2*)&g_h_half[(long)row0 * DHID + col] =
                    __floats2half2_rn(c[mt][nt][0], c[mt][nt][1]);
            if (row0 + 8 < N_NODES)
                *(__half2*)&g_h_half[(long)(row0 + 8) * DHID + col] =
                    __floats2half2_rn(c[mt][nt][2], c[mt][nt][3]);
        }
    }

    // ---- fused attention scores (block owns heads 2*by, 2*by+1) ----
    int head_l = wn >> 6;
    int slot   = (wn >> 5) & 1;
    float attS[4][2], attD[4][2];
    #pragma unroll
    for (int nt = 0; nt < 4; nt++)
        #pragma unroll
        for (int j = 0; j < 2; j++) {
            int col = bn + wn + nt * 8 + 2 * lc + j;
            attS[nt][j] = att_src[col];
            attD[nt][j] = att_dst[col];
        }
    __syncthreads();
    #pragma unroll
    for (int mt = 0; mt < 4; mt++) {
        float s0 = 0.f, d0 = 0.f, s1 = 0.f, d1 = 0.f;
        #pragma unroll
        for (int nt = 0; nt < 4; nt++) {
            s0 += c[mt][nt][0] * attS[nt][0] + c[mt][nt][1] * attS[nt][1];
            d0 += c[mt][nt][0] * attD[nt][0] + c[mt][nt][1] * attD[nt][1];
            s1 += c[mt][nt][2] * attS[nt][0] + c[mt][nt][3] * attS[nt][1];
            d1 += c[mt][nt][2] * attD[nt][0] + c[mt][nt][3] * attD[nt][1];
        }
        #pragma unroll
        for (int o = 1; o < 4; o <<= 1) {
            s0 += __shfl_xor_sync(0xFFFFFFFFu, s0, o);
            d0 += __shfl_xor_sync(0xFFFFFFFFu, d0, o);
            s1 += __shfl_xor_sync(0xFFFFFFFFu, s1, o);
            d1 += __shfl_xor_sync(0xFFFFFFFFu, d1, o);
        }
        if (lc == 0) {
            int r0 = wm + mt * 16 + lr;
            s_attn[((0 * 2 + head_l) * 2 + slot) * BM + r0]     = s0;
            s_attn[((1 * 2 + head_l) * 2 + slot) * BM + r0]     = d0;
            s_attn[((0 * 2 + head_l) * 2 + slot) * BM + r0 + 8] = s1;
            s_attn[((1 * 2 + head_l) * 2 + slot) * BM + r0 + 8] = d1;
        }
    }
    __syncthreads();
    {
        int row = tid & 127;
        int hl  = tid >> 7;
        int node = bm + row;
        if (node < N_NODES) {
            int hg = blockIdx.y * 2 + hl;
            g_asrc[node * 4 + hg] = s_attn[((0 * 2 + hl) * 2 + 0) * BM + row]
                                  + s_attn[((0 * 2 + hl) * 2 + 1) * BM + row];
            g_adst[node * 4 + hg] = s_attn[((1 * 2 + hl) * 2 + 0) * BM + row]
                                  + s_attn[((1 * 2 + hl) * 2 + 1) * BM + row];
        }
    }
}

// ========================= fused aggregate (warp per node) ====================
__device__ __forceinline__ float4 eexp4(float4 a, float4 b) {
    float4 e;
    e.x = a.x + b.x; e.y = a.y + b.y; e.z = a.z + b.z; e.w = a.w + b.w;
    e.x = (e.x > 0.f) ? e.x : 0.2f * e.x;
    e.y = (e.y > 0.f) ? e.y : 0.2f * e.y;
    e.z = (e.z > 0.f) ? e.z : 0.2f * e.z;
    e.w = (e.w > 0.f) ? e.w : 0.2f * e.w;
    e.x = __expf(e.x); e.y = __expf(e.y); e.z = __expf(e.z); e.w = __expf(e.w);
    return e;
}

__device__ __forceinline__ void fma8(float* acc, float alpha, uint4 raw) {
    float2 f0 = __half22float2(*(__half2*)&raw.x);
    float2 f1 = __half22float2(*(__half2*)&raw.y);
    float2 f2 = __half22float2(*(__half2*)&raw.z);
    float2 f3 = __half22float2(*(__half2*)&raw.w);
    acc[0] += alpha * f0.x; acc[1] += alpha * f0.y;
    acc[2] += alpha * f1.x; acc[3] += alpha * f1.y;
    acc[4] += alpha * f2.x; acc[5] += alpha * f2.y;
    acc[6] += alpha * f3.x; acc[7] += alpha * f3.y;
}

__global__ __launch_bounds__(256) void gat_aggregate_kernel(
    const float* __restrict__ bias, float* __restrict__ dst_ext, int to_act)
{
    int n    = (blockIdx.x * blockDim.x + threadIdx.x) >> 5;
    int lane = threadIdx.x & 31;
    if (n >= N_NODES) return;
    int beg = g_rowptr[n];
    int end = g_rowptr[n + 1];
    float4 adst = *(const float4*)&g_adst[n * 4];

    // pass 1: denominator
    float4 dsum = make_float4(0.f, 0.f, 0.f, 0.f);
    for (int e = beg + lane; e < end; e += 32) {
        int s = g_csr_src[e];
        float4 a = *(const float4*)&g_asrc[s * 4];
        float4 ee = eexp4(a, adst);
        dsum.x += ee.x; dsum.y += ee.y; dsum.z += ee.z; dsum.w += ee.w;
    }
    #pragma unroll
    for (int o = 16; o > 0; o >>= 1) {
        dsum.x += __shfl_xor_sync(0xFFFFFFFFu, dsum.x, o);
        dsum.y += __shfl_xor_sync(0xFFFFFFFFu, dsum.y, o);
        dsum.z += __shfl_xor_sync(0xFFFFFFFFu, dsum.z, o);
        dsum.w += __shfl_xor_sync(0xFFFFFFFFu, dsum.w, o);
    }
    int head = lane >> 3;
    float den = (head == 0) ? dsum.x : (head == 1) ? dsum.y : (head == 2) ? dsum.z : dsum.w;
    float inv = 1.f / (den + 1e-16f);
    float adst_h = (head == 0) ? adst.x : (head == 1) ? adst.y : (head == 2) ? adst.z : adst.w;

    // pass 2: scalar per-head score, unrolled x4
    float acc[8] = {0.f, 0.f, 0.f, 0.f, 0.f, 0.f, 0.f, 0.f};
    int e = beg;
    for (; e + 4 <= end; e += 4) {
        int i0 = g_csr_src[e];
        int i1 = g_csr_src[e + 1];
        int i2 = g_csr_src[e + 2];
        int i3 = g_csr_src[e + 3];
        float a0 = __ldg(&g_asrc[i0 * 4 + head]);
        float a1 = __ldg(&g_asrc[i1 * 4 + head]);
        float a2 = __ldg(&g_asrc[i2 * 4 + head]);
        float a3 = __ldg(&g_asrc[i3 * 4 + head]);
        uint4 r0 = *(const uint4*)&g_h_half[(long)i0 * DHID + lane * 8];
        uint4 r1 = *(const uint4*)&g_h_half[(long)i1 * DHID + lane * 8];
        uint4 r2 = *(const uint4*)&g_h_half[(long)i2 * DHID + lane * 8];
        uint4 r3 = *(const uint4*)&g_h_half[(long)i3 * DHID + lane * 8];
        float e0 = a0 + adst_h; e0 = (e0 > 0.f) ? e0 : 0.2f * e0;
        float e1 = a1 + adst_h; e1 = (e1 > 0.f) ? e1 : 0.2f * e1;
        float e2 = a2 + adst_h; e2 = (e2 > 0.f) ? e2 : 0.2f * e2;
        float e3 = a3 + adst_h; e3 = (e3 > 0.f) ? e3 : 0.2f * e3;
        fma8(acc, __expf(e0) * inv, r0);
        fma8(acc, __expf(e1) * inv, r1);
        fma8(acc, __expf(e2) * inv, r2);
        fma8(acc, __expf(e3) * inv, r3);
    }
    for (; e < end; e++) {
        int i0 = g_csr_src[e];
        float a0 = __ldg(&g_asrc[i0 * 4 + head]);
        uint4 r0 = *(const uint4*)&g_h_half[(long)i0 * DHID + lane * 8];
        float e0 = a0 + adst_h; e0 = (e0 > 0.f) ? e0 : 0.2f * e0;
        fma8(acc, __expf(e0) * inv, r0);
    }

    // epilogue: bias + ELU + store
    float4 b0 = ((const float4*)bias)[lane * 2];
    float4 b1 = ((const float4*)bias)[lane * 2 + 1];
    float bb[8] = {b0.x, b0.y, b0.z, b0.w, b1.x, b1.y, b1.z, b1.w};
    #pragma unroll
    for (int i = 0; i < 8; i++) {
        float v = acc[i] + bb[i];
        acc[i] = (v > 0.f) ? v : expm1f(v);
    }
    if (to_act) {
        __half2 h0 = __floats2half2_rn(acc[0], acc[1]);
        __half2 h1 = __floats2half2_rn(acc[2], acc[3]);
        __half2 h2 = __floats2half2_rn(acc[4], acc[5]);
        __half2 h3 = __floats2half2_rn(acc[6], acc[7]);
        uint4 packed = make_uint4(*(uint32_t*)&h0, *(uint32_t*)&h1,
                                  *(uint32_t*)&h2, *(uint32_t*)&h3);
        *(uint4*)&g_act[(long)n * DHID + lane * 8] = packed;
    } else {
        float* op = &dst_ext[(long)n * DHID + lane * 8];
        *(float4*)op       = make_float4(acc[0], acc[1], acc[2], acc[3]);
        *(float4*)(op + 4) = make_float4(acc[4], acc[5], acc[6], acc[7]);
    }
}

// ========================= launch =========================
extern "C" void kernel_launch(void* const* d_in, const int* in_sizes, int n_in,
                              void* d_out, int out_size)
{
    const float* x   = (const float*)d_in[0];
    const int*   ei  = (const int*)  d_in[1];
    const float* W1  = (const float*)d_in[2];
    const float* as1 = (const float*)d_in[3];
    const float* ad1 = (const float*)d_in[4];
    const float* b1  = (const float*)d_in[5];
    const float* W2  = (const float*)d_in[6];
    const float* as2 = (const float*)d_in[7];
    const float* ad2 = (const float*)d_in[8];
    const float* b2  = (const float*)d_in[9];
    float* out = (float*)d_out;

    cudaStream_t s0 = 0;           // legacy default (captured stream)
    cudaStream_t s2 = g_gs.s2;

    dim3 gemm_grid((N_NODES + BM - 1) / BM, DHID / BN);
    int edge_blocks = (TOT_EDGES + 255) / 256;
    int agg_blocks  = (N_NODES + 7) / 8;
    int cvtx_blocks = (N_NODES * KDIM / 8 + 255) / 256;
    dim3 wgrid(8, 8, 2), wblk(32, 8);

    // fork point
    cudaEventRecord(g_gs.ev0, s0);
    cudaStreamWaitEvent(s2, g_gs.ev0, 0);

    // ---- s0: convert x (+zero deg), then CSR build ----
    convert_x_kernel<<<cvtx_blocks, 256, 0, s0>>>(x);
    cudaEventRecord(g_gs.evX, s0);
    count_kernel<<<edge_blocks, 256, 0, s0>>>(ei);
    block_reduce_kernel<<<NBLK, 256, 0, s0>>>();
    scan_blocks_kernel<<<1, 256, 0, s0>>>();
    scatter_rowptr_kernel<<<NBLK, 256, 0, s0>>>();
    fill_kernel<<<edge_blocks, 256, 0, s0>>>(ei);

    // ---- s2: weights + layer-1 GEMM (needs x conversion) ----
    convert_w_kernel<<<wgrid, wblk, 0, s2>>>(W1, W2);
    cudaStreamWaitEvent(s2, g_gs.evX, 0);
    gemm_f16_kernel<<<gemm_grid, 256, 0, s2>>>(0, as1, ad1);
    cudaEventRecord(g_gs.evG1, s2);

    // ---- s0: join, then the serial tail ----
    cudaStreamWaitEvent(s0, g_gs.evG1, 0);
    gat_aggregate_kernel<<<agg_blocks, 256, 0, s0>>>(b1, nullptr, 1);
    gemm_f16_kernel<<<gemm_grid, 256, 0, s0>>>(1, as2, ad2);
    gat_aggregate_kernel<<<agg_blocks, 256, 0, s0>>>(b2, out, 0);
}

// round 10
// speedup vs baseline: 1.0687x; 1.0340x over previous
#include <cuda_runtime.h>
#include <cuda_fp16.h>
#include <math.h>
#include <stdint.h>

#define N_NODES   50000
#define N_EDGES   800000
#define TOT_EDGES (N_EDGES + N_NODES)
#define HEADS     4
#define OUT_CH    64
#define DHID      256
#define KDIM      256
#define NBLK      196        // ceil(N_NODES/256)

// ---------------- scratch (static device globals; no allocation) ------------
__device__ __half g_h_half[N_NODES * DHID];
__device__ __half g_act[N_NODES * DHID];
__device__ __half g_w1t[DHID * KDIM];
__device__ __half g_w2t[DHID * KDIM];
__device__ float  g_asrc[N_NODES * HEADS];
__device__ float  g_adst[N_NODES * HEADS];
__device__ int    g_deg[N_NODES];
__device__ int    g_rowptr[N_NODES + 1];
__device__ int    g_cursor[N_NODES];
__device__ int    g_csr_src[TOT_EDGES];
__device__ int    g_blocksums[256];

// ---------------- streams/events (created at load time) ---------------------
struct GraphStreams {
    cudaStream_t s2 = nullptr;
    cudaEvent_t ev0 = nullptr, evG1 = nullptr;
    GraphStreams() {
        cudaStreamCreateWithFlags(&s2, cudaStreamNonBlocking);
        cudaEventCreateWithFlags(&ev0, cudaEventDisableTiming);
        cudaEventCreateWithFlags(&evG1, cudaEventDisableTiming);
    }
};
static GraphStreams g_gs;

__device__ __forceinline__ void cp_async16(uint32_t smem_dst, const void* gsrc, int src_bytes) {
    asm volatile("cp.async.cg.shared.global [%0], [%1], 16, %2;"
                 :: "r"(smem_dst), "l"(gsrc), "r"(src_bytes));
}

__device__ __forceinline__ void ldsm_x4(uint32_t& r0, uint32_t& r1,
                                        uint32_t& r2, uint32_t& r3,
                                        const void* smem_ptr) {
    uint32_t addr = (uint32_t)__cvta_generic_to_shared(smem_ptr);
    asm volatile("ldmatrix.sync.aligned.m8n8.x4.shared.b16 {%0,%1,%2,%3}, [%4];"
                 : "=r"(r0), "=r"(r1), "=r"(r2), "=r"(r3) : "r"(addr));
}

// ========================= weight conversion =========================
__global__ void convert_w_kernel(const float* __restrict__ W1,
                                 const float* __restrict__ W2) {
    const float* W = blockIdx.z ? W2 : W1;
    __half* Wt = blockIdx.z ? g_w2t : g_w1t;
    __shared__ float tile[32][33];
    int bx = blockIdx.x * 32, by = blockIdx.y * 32;
    int tx = threadIdx.x, ty = threadIdx.y;   // block (32, 8)
    #pragma unroll
    for (int i = 0; i < 32; i += 8)
        tile[ty + i][tx] = W[(by + ty + i) * DHID + bx + tx];
    __syncthreads();
    #pragma unroll
    for (int i = 0; i < 32; i += 8)
        Wt[(bx + ty + i) * KDIM + by + tx] = __float2half(tile[tx][ty + i]);
}

// ========================= CSR build =========================
__global__ void zero_deg_kernel() {
    int i = blockIdx.x * blockDim.x + threadIdx.x;
    if (i < N_NODES) g_deg[i] = 0;
}

__global__ void count_kernel(const int* __restrict__ ei) {
    int i = blockIdx.x * blockDim.x + threadIdx.x;
    if (i >= TOT_EDGES) return;
    int d = (i < N_EDGES) ? ei[N_EDGES + i] : (i - N_EDGES);
    atomicAdd(&g_deg[d], 1);
}

__global__ void block_reduce_kernel() {
    __shared__ int sh[256];
    int t = threadIdx.x;
    int i = blockIdx.x * 256 + t;
    sh[t] = (i < N_NODES) ? g_deg[i] : 0;
    __syncthreads();
    for (int o = 128; o > 0; o >>= 1) {
        if (t < o) sh[t] += sh[t + o];
        __syncthreads();
    }
    if (t == 0) g_blocksums[blockIdx.x] = sh[0];
}

__global__ void scan_blocks_kernel() {
    __shared__ int sh[256];
    int t = threadIdx.x;
    int v = (t < NBLK) ? g_blocksums[t] : 0;
    sh[t] = v;
    __syncthreads();
    for (int o = 1; o < 256; o <<= 1) {
        int x = (t >= o) ? sh[t - o] : 0;
        __syncthreads();
        sh[t] += x;
        __syncthreads();
    }
    if (t < NBLK) g_blocksums[t] = sh[t] - v;
}

__global__ void scatter_rowptr_kernel() {
    __shared__ int sh[256];
    int t = threadIdx.x;
    int i = blockIdx.x * 256 + t;
    int v = (i < N_NODES) ? g_deg[i] : 0;
    sh[t] = v;
    __syncthreads();
    for (int o = 1; o < 256; o <<= 1) {
        int x = (t >= o) ? sh[t - o] : 0;
        __syncthreads();
        sh[t] += x;
        __syncthreads();
    }
    int off = g_blocksums[blockIdx.x];
    if (i < N_NODES) {
        int r = off + sh[t] - v;
        g_rowptr[i] = r;
        g_cursor[i] = r;
        if (i == N_NODES - 1) g_rowptr[N_NODES] = TOT_EDGES;
    }
}

__global__ void fill_kernel(const int* __restrict__ ei) {
    int i = blockIdx.x * blockDim.x + threadIdx.x;
    if (i >= TOT_EDGES) return;
    int s, d;
    if (i < N_EDGES) { s = ei[i]; d = ei[N_EDGES + i]; }
    else             { s = d = i - N_EDGES; }
    int pos = atomicAdd(&g_cursor[d], 1);
    g_csr_src[pos] = s;
}

// ========================= fp16 GEMM + fused attn + fp16 store ===============
// layer 0: A = x (fp32, converted in the loader). layer 1: A = g_act (half).
#define BM 128
#define BN 128
#define BK 32
#define STRH 40

__global__ __launch_bounds__(256) void gemm_f16_kernel(
    int layer, const float* __restrict__ x32,
    const float* __restrict__ att_src, const float* __restrict__ att_dst)
{
    const __half* A  = (const __half*)g_act;     // layer 1 only
    const __half* Bt = layer ? (const __half*)g_w2t : (const __half*)g_w1t;

    __shared__ __half As[2][BM][STRH];
    __shared__ __half Bs[2][BN][STRH];
    float* s_attn = (float*)As;

    int bm = blockIdx.x * BM;
    int bn = blockIdx.y * BN;
    int tid  = threadIdx.x;
    int warp = tid >> 5;
    int lane = tid & 31;
    int wm = (warp & 1) * 64;
    int wn = (warp >> 1) * 32;
    int lr = lane >> 2;
    int lc = lane & 3;
    int lg = lane >> 3;     // ldmatrix group 0..3
    int rl = lane & 7;      // row within group

    float c[4][4][4];
    #pragma unroll
    for (int mt = 0; mt < 4; mt++)
        #pragma unroll
        for (int nt = 0; nt < 4; nt++)
            #pragma unroll
            for (int f = 0; f < 4; f++) c[mt][nt][f] = 0.f;

    // ---- B loader (always half, cp.async) ----
    auto load_B = [&](int st, int k0) {
        #pragma unroll
        for (int i = 0; i < 2; i++) {
            int idx = tid + i * 256;
            int r = idx >> 2;
            int cg = (idx & 3) * 8;
            uint32_t dst = (uint32_t)__cvta_generic_to_shared(&Bs[st][r][cg]);
            cp_async16(dst, &Bt[(long)(bn + r) * KDIM + k0 + cg], 16);
        }
    };
    // ---- A loader, layer 1 (half, cp.async) ----
    auto load_A_h = [&](int st, int k0) {
        #pragma unroll
        for (int i = 0; i < 2; i++) {
            int idx = tid + i * 256;
            int r = idx >> 2;
            int cg = (idx & 3) * 8;
            int gr = bm + r;
            int valid = (gr < N_NODES);
            int src_row = valid ? gr : 0;
            uint32_t dst = (uint32_t)__cvta_generic_to_shared(&As[st][r][cg]);
            cp_async16(dst, &A[(long)src_row * KDIM + k0 + cg], valid ? 16 : 0);
        }
    };
    // ---- A loader, layer 0 (fp32 -> regs; STS later) ----
    // tile = 128 rows x 32 fp32 = 1024 float4; 256 thr x 4
    float4 areg[4];
    auto ldg_A_f = [&](int k0) {
        #pragma unroll
        for (int i = 0; i < 4; i++) {
            int idx = tid + i * 256;
            int r = idx >> 3;           // 0..127
            int cg = (idx & 7) * 4;     // fp32 col group
            int gr = bm + r;
            if (gr < N_NODES)
                areg[i] = *(const float4*)&x32[(long)gr * KDIM + k0 + cg];
            else
                areg[i] = make_float4(0.f, 0.f, 0.f, 0.f);
        }
    };
    auto sts_A_f = [&](int st) {
        #pragma unroll
        for (int i = 0; i < 4; i++) {
            int idx = tid + i * 256;
            int r = idx >> 3;
            int cg = (idx & 7) * 4;     // col in elements (halfs)
            __half2 h01 = __floats2half2_rn(areg[i].x, areg[i].y);
            __half2 h23 = __floats2half2_rn(areg[i].z, areg[i].w);
            *(uint2*)&As[st][r][cg] = make_uint2(*(uint32_t*)&h01, *(uint32_t*)&h23);
        }
    };

    // ---- prologue: stage 0 ----
    if (layer) {
        load_A_h(0, 0);
    } else {
        ldg_A_f(0);
        sts_A_f(0);
    }
    load_B(0, 0);
    asm volatile("cp.async.commit_group;");

    const int NITER = KDIM / BK;   // 8
    #pragma unroll 1
    for (int it = 0; it < NITER; it++) {
        int nxt = (it + 1) & 1;
        if (it + 1 < NITER) {
            if (layer) load_A_h(nxt, (it + 1) * BK);
            else       ldg_A_f((it + 1) * BK);          // async LDG into regs
            load_B(nxt, (it + 1) * BK);
            asm volatile("cp.async.commit_group;");
            asm volatile("cp.async.wait_group 1;");
        } else {
            asm volatile("cp.async.wait_group 0;");
        }
        __syncthreads();
        int st = it & 1;

        #pragma unroll
        for (int ks = 0; ks < 2; ks++) {
            int k = ks * 16;
            uint32_t af[4][4];
            #pragma unroll
            for (int mt = 0; mt < 4; mt++) {
                const __half* p = &As[st][wm + mt * 16 + ((lg & 1) << 3) + rl]
                                        [k + ((lg >> 1) << 3)];
                ldsm_x4(af[mt][0], af[mt][1], af[mt][2], af[mt][3], p);
            }
            uint32_t bf[4][2];
            #pragma unroll
            for (int p2 = 0; p2 < 2; p2++) {
                int ntb = p2 * 2 + (lg >> 1);
                const __half* p = &Bs[st][wn + ntb * 8 + rl][k + ((lg & 1) << 3)];
                ldsm_x4(bf[p2 * 2][0], bf[p2 * 2][1],
                        bf[p2 * 2 + 1][0], bf[p2 * 2 + 1][1], p);
            }
            #pragma unroll
            for (int mt = 0; mt < 4; mt++)
                #pragma unroll
                for (int nt = 0; nt < 4; nt++) {
                    asm volatile(
                        "mma.sync.aligned.m16n8k16.row.col.f32.f16.f16.f32 "
                        "{%0,%1,%2,%3}, {%4,%5,%6,%7}, {%8,%9}, {%0,%1,%2,%3};"
                        : "+f"(c[mt][nt][0]), "+f"(c[mt][nt][1]),
                          "+f"(c[mt][nt][2]), "+f"(c[mt][nt][3])
                        : "r"(af[mt][0]), "r"(af[mt][1]), "r"(af[mt][2]), "r"(af[mt][3]),
                          "r"(bf[nt][0]), "r"(bf[nt][1]));
                }
        }
        if (!layer && it + 1 < NITER) sts_A_f(nxt);   // LDG issued pre-MMA, now landed
        __syncthreads();
    }

    // ---- store C as fp16 ----
    #pragma unroll
    for (int mt = 0; mt < 4; mt++) {
        int row0 = bm + wm + mt * 16 + lr;
        #pragma unroll
        for (int nt = 0; nt < 4; nt++) {
            int col = bn + wn + nt * 8 + 2 * lc;
            if (row0 < N_NODES)
                *(__half2*)&g_h_half[(long)row0 * DHID + col] =
                    __floats2half2_rn(c[mt][nt][0], c[mt][nt][1]);
            if (row0 + 8 < N_NODES)
                *(__half2*)&g_h_half[(long)(row0 + 8) * DHID + col] =
                    __floats2half2_rn(c[mt][nt][2], c[mt][nt][3]);
        }
    }

    // ---- fused attention scores (block owns heads 2*by, 2*by+1) ----
    int head_l = wn >> 6;
    int slot   = (wn >> 5) & 1;
    float attS[4][2], attD[4][2];
    #pragma unroll
    for (int nt = 0; nt < 4; nt++)
        #pragma unroll
        for (int j = 0; j < 2; j++) {
            int col = bn + wn + nt * 8 + 2 * lc + j;
            attS[nt][j] = att_src[col];
            attD[nt][j] = att_dst[col];
        }
    __syncthreads();
    #pragma unroll
    for (int mt = 0; mt < 4; mt++) {
        float s0 = 0.f, d0 = 0.f, s1 = 0.f, d1 = 0.f;
        #pragma unroll
        for (int nt = 0; nt < 4; nt++) {
            s0 += c[mt][nt][0] * attS[nt][0] + c[mt][nt][1] * attS[nt][1];
            d0 += c[mt][nt][0] * attD[nt][0] + c[mt][nt][1] * attD[nt][1];
            s1 += c[mt][nt][2] * attS[nt][0] + c[mt][nt][3] * attS[nt][1];
            d1 += c[mt][nt][2] * attD[nt][0] + c[mt][nt][3] * attD[nt][1];
        }
        #pragma unroll
        for (int o = 1; o < 4; o <<= 1) {
            s0 += __shfl_xor_sync(0xFFFFFFFFu, s0, o);
            d0 += __shfl_xor_sync(0xFFFFFFFFu, d0, o);
            s1 += __shfl_xor_sync(0xFFFFFFFFu, s1, o);
            d1 += __shfl_xor_sync(0xFFFFFFFFu, d1, o);
        }
        if (lc == 0) {
            int r0 = wm + mt * 16 + lr;
            s_attn[((0 * 2 + head_l) * 2 + slot) * BM + r0]     = s0;
            s_attn[((1 * 2 + head_l) * 2 + slot) * BM + r0]     = d0;
            s_attn[((0 * 2 + head_l) * 2 + slot) * BM + r0 + 8] = s1;
            s_attn[((1 * 2 + head_l) * 2 + slot) * BM + r0 + 8] = d1;
        }
    }
    __syncthreads();
    {
        int row = tid & 127;
        int hl  = tid >> 7;
        int node = bm + row;
        if (node < N_NODES) {
            int hg = blockIdx.y * 2 + hl;
            g_asrc[node * 4 + hg] = s_attn[((0 * 2 + hl) * 2 + 0) * BM + row]
                                  + s_attn[((0 * 2 + hl) * 2 + 1) * BM + row];
            g_adst[node * 4 + hg] = s_attn[((1 * 2 + hl) * 2 + 0) * BM + row]
                                  + s_attn[((1 * 2 + hl) * 2 + 1) * BM + row];
        }
    }
}

// ========================= fused aggregate (warp per node) ====================
__device__ __forceinline__ float4 eexp4(float4 a, float4 b) {
    float4 e;
    e.x = a.x + b.x; e.y = a.y + b.y; e.z = a.z + b.z; e.w = a.w + b.w;
    e.x = (e.x > 0.f) ? e.x : 0.2f * e.x;
    e.y = (e.y > 0.f) ? e.y : 0.2f * e.y;
    e.z = (e.z > 0.f) ? e.z : 0.2f * e.z;
    e.w = (e.w > 0.f) ? e.w : 0.2f * e.w;
    e.x = __expf(e.x); e.y = __expf(e.y); e.z = __expf(e.z); e.w = __expf(e.w);
    return e;
}

__device__ __forceinline__ void fma8(float* acc, float alpha, uint4 raw) {
    float2 f0 = __half22float2(*(__half2*)&raw.x);
    float2 f1 = __half22float2(*(__half2*)&raw.y);
    float2 f2 = __half22float2(*(__half2*)&raw.z);
    float2 f3 = __half22float2(*(__half2*)&raw.w);
    acc[0] += alpha * f0.x; acc[1] += alpha * f0.y;
    acc[2] += alpha * f1.x; acc[3] += alpha * f1.y;
    acc[4] += alpha * f2.x; acc[5] += alpha * f2.y;
    acc[6] += alpha * f3.x; acc[7] += alpha * f3.y;
}

__global__ __launch_bounds__(256) void gat_aggregate_kernel(
    const float* __restrict__ bias, float* __restrict__ dst_ext, int to_act)
{
    int n    = (blockIdx.x * blockDim.x + threadIdx.x) >> 5;
    int lane = threadIdx.x & 31;
    if (n >= N_NODES) return;
    int beg = g_rowptr[n];
    int end = g_rowptr[n + 1];
    float4 adst = *(const float4*)&g_adst[n * 4];

    // pass 1: denominator
    float4 dsum = make_float4(0.f, 0.f, 0.f, 0.f);
    for (int e = beg + lane; e < end; e += 32) {
        int s = g_csr_src[e];
        float4 a = *(const float4*)&g_asrc[s * 4];
        float4 ee = eexp4(a, adst);
        dsum.x += ee.x; dsum.y += ee.y; dsum.z += ee.z; dsum.w += ee.w;
    }
    #pragma unroll
    for (int o = 16; o > 0; o >>= 1) {
        dsum.x += __shfl_xor_sync(0xFFFFFFFFu, dsum.x, o);
        dsum.y += __shfl_xor_sync(0xFFFFFFFFu, dsum.y, o);
        dsum.z += __shfl_xor_sync(0xFFFFFFFFu, dsum.z, o);
        dsum.w += __shfl_xor_sync(0xFFFFFFFFu, dsum.w, o);
    }
    int head = lane >> 3;
    float den = (head == 0) ? dsum.x : (head == 1) ? dsum.y : (head == 2) ? dsum.z : dsum.w;
    float inv = 1.f / (den + 1e-16f);
    float adst_h = (head == 0) ? adst.x : (head == 1) ? adst.y : (head == 2) ? adst.z : adst.w;

    // pass 2: scalar per-head score, unrolled x4
    float acc[8] = {0.f, 0.f, 0.f, 0.f, 0.f, 0.f, 0.f, 0.f};
    int e = beg;
    for (; e + 4 <= end; e += 4) {
        int i0 = g_csr_src[e];
        int i1 = g_csr_src[e + 1];
        int i2 = g_csr_src[e + 2];
        int i3 = g_csr_src[e + 3];
        float a0 = __ldg(&g_asrc[i0 * 4 + head]);
        float a1 = __ldg(&g_asrc[i1 * 4 + head]);
        float a2 = __ldg(&g_asrc[i2 * 4 + head]);
        float a3 = __ldg(&g_asrc[i3 * 4 + head]);
        uint4 r0 = *(const uint4*)&g_h_half[(long)i0 * DHID + lane * 8];
        uint4 r1 = *(const uint4*)&g_h_half[(long)i1 * DHID + lane * 8];
        uint4 r2 = *(const uint4*)&g_h_half[(long)i2 * DHID + lane * 8];
        uint4 r3 = *(const uint4*)&g_h_half[(long)i3 * DHID + lane * 8];
        float e0 = a0 + adst_h; e0 = (e0 > 0.f) ? e0 : 0.2f * e0;
        float e1 = a1 + adst_h; e1 = (e1 > 0.f) ? e1 : 0.2f * e1;
        float e2 = a2 + adst_h; e2 = (e2 > 0.f) ? e2 : 0.2f * e2;
        float e3 = a3 + adst_h; e3 = (e3 > 0.f) ? e3 : 0.2f * e3;
        fma8(acc, __expf(e0) * inv, r0);
        fma8(acc, __expf(e1) * inv, r1);
        fma8(acc, __expf(e2) * inv, r2);
        fma8(acc, __expf(e3) * inv, r3);
    }
    for (; e < end; e++) {
        int i0 = g_csr_src[e];
        float a0 = __ldg(&g_asrc[i0 * 4 + head]);
        uint4 r0 = *(const uint4*)&g_h_half[(long)i0 * DHID + lane * 8];
        float e0 = a0 + adst_h; e0 = (e0 > 0.f) ? e0 : 0.2f * e0;
        fma8(acc, __expf(e0) * inv, r0);
    }

    // epilogue: bias + ELU + store
    float4 b0 = ((const float4*)bias)[lane * 2];
    float4 b1 = ((const float4*)bias)[lane * 2 + 1];
    float bb[8] = {b0.x, b0.y, b0.z, b0.w, b1.x, b1.y, b1.z, b1.w};
    #pragma unroll
    for (int i = 0; i < 8; i++) {
        float v = acc[i] + bb[i];
        acc[i] = (v > 0.f) ? v : expm1f(v);
    }
    if (to_act) {
        __half2 h0 = __floats2half2_rn(acc[0], acc[1]);
        __half2 h1 = __floats2half2_rn(acc[2], acc[3]);
        __half2 h2 = __floats2half2_rn(acc[4], acc[5]);
        __half2 h3 = __floats2half2_rn(acc[6], acc[7]);
        uint4 packed = make_uint4(*(uint32_t*)&h0, *(uint32_t*)&h1,
                                  *(uint32_t*)&h2, *(uint32_t*)&h3);
        *(uint4*)&g_act[(long)n * DHID + lane * 8] = packed;
    } else {
        float* op = &dst_ext[(long)n * DHID + lane * 8];
        *(float4*)op       = make_float4(acc[0], acc[1], acc[2], acc[3]);
        *(float4*)(op + 4) = make_float4(acc[4], acc[5], acc[6], acc[7]);
    }
}

// ========================= launch =========================
extern "C" void kernel_launch(void* const* d_in, const int* in_sizes, int n_in,
                              void* d_out, int out_size)
{
    const float* x   = (const float*)d_in[0];
    const int*   ei  = (const int*)  d_in[1];
    const float* W1  = (const float*)d_in[2];
    const float* as1 = (const float*)d_in[3];
    const float* ad1 = (const float*)d_in[4];
    const float* b1  = (const float*)d_in[5];
    const float* W2  = (const float*)d_in[6];
    const float* as2 = (const float*)d_in[7];
    const float* ad2 = (const float*)d_in[8];
    const float* b2  = (const float*)d_in[9];
    float* out = (float*)d_out;

    cudaStream_t s0 = 0;           // legacy default (captured stream)
    cudaStream_t s2 = g_gs.s2;

    dim3 gemm_grid((N_NODES + BM - 1) / BM, DHID / BN);
    int edge_blocks = (TOT_EDGES + 255) / 256;
    int agg_blocks  = (N_NODES + 7) / 8;
    dim3 wgrid(8, 8, 2), wblk(32, 8);

    // fork point
    cudaEventRecord(g_gs.ev0, s0);
    cudaStreamWaitEvent(s2, g_gs.ev0, 0);

    // ---- s0: CSR build (starts immediately) ----
    zero_deg_kernel<<<NBLK, 256, 0, s0>>>();
    count_kernel<<<edge_blocks, 256, 0, s0>>>(ei);
    block_reduce_kernel<<<NBLK, 256, 0, s0>>>();
    scan_blocks_kernel<<<1, 256, 0, s0>>>();
    scatter_rowptr_kernel<<<NBLK, 256, 0, s0>>>();
    fill_kernel<<<edge_blocks, 256, 0, s0>>>(ei);

    // ---- s2: weights + layer-1 GEMM (reads fp32 x directly) ----
    convert_w_kernel<<<wgrid, wblk, 0, s2>>>(W1, W2);
    gemm_f16_kernel<<<gemm_grid, 256, 0, s2>>>(0, x, as1, ad1);
    cudaEventRecord(g_gs.evG1, s2);

    // ---- s0: join, then the serial tail ----
    cudaStreamWaitEvent(s0, g_gs.evG1, 0);
    gat_aggregate_kernel<<<agg_blocks, 256, 0, s0>>>(b1, nullptr, 1);
    gemm_f16_kernel<<<gemm_grid, 256, 0, s0>>>(1, nullptr, as2, ad2);
    gat_aggregate_kernel<<<agg_blocks, 256, 0, s0>>>(b2, out, 0);
}

// round 11
// speedup vs baseline: 1.1445x; 1.0709x over previous
#include <cuda_runtime.h>
#include <cuda_fp16.h>
#include <math.h>
#include <stdint.h>

#define N_NODES   50000
#define N_EDGES   800000
#define TOT_EDGES (N_EDGES + N_NODES)
#define HEADS     4
#define OUT_CH    64
#define DHID      256
#define KDIM      256
#define NBLK      196        // ceil(N_NODES/256)

// ---------------- scratch (static device globals; no allocation) ------------
__device__ __half g_h_half[N_NODES * DHID];
__device__ __half g_act[N_NODES * DHID];
__device__ __half g_w1t[DHID * KDIM];
__device__ __half g_w2t[DHID * KDIM];
__device__ float  g_asrc[N_NODES * HEADS];
__device__ float  g_adst[N_NODES * HEADS];
__device__ int    g_deg[N_NODES];
__device__ int    g_rowptr[N_NODES + 1];
__device__ int    g_cursor[N_NODES];
__device__ int    g_csr_src[TOT_EDGES];
__device__ int    g_blocksums[256];

// ---------------- streams/events (created at load time) ---------------------
struct GraphStreams {
    cudaStream_t s2 = nullptr;
    cudaEvent_t ev0 = nullptr, evG1 = nullptr;
    GraphStreams() {
        cudaStreamCreateWithFlags(&s2, cudaStreamNonBlocking);
        cudaEventCreateWithFlags(&ev0, cudaEventDisableTiming);
        cudaEventCreateWithFlags(&evG1, cudaEventDisableTiming);
    }
};
static GraphStreams g_gs;

__device__ __forceinline__ void cp_async16(uint32_t smem_dst, const void* gsrc, int src_bytes) {
    asm volatile("cp.async.cg.shared.global [%0], [%1], 16, %2;"
                 :: "r"(smem_dst), "l"(gsrc), "r"(src_bytes));
}

__device__ __forceinline__ void ldsm_x4(uint32_t& r0, uint32_t& r1,
                                        uint32_t& r2, uint32_t& r3,
                                        const void* smem_ptr) {
    uint32_t addr = (uint32_t)__cvta_generic_to_shared(smem_ptr);
    asm volatile("ldmatrix.sync.aligned.m8n8.x4.shared.b16 {%0,%1,%2,%3}, [%4];"
                 : "=r"(r0), "=r"(r1), "=r"(r2), "=r"(r3) : "r"(addr));
}

// ========================= weight conversion =========================
__global__ void convert_w_kernel(const float* __restrict__ W1,
                                 const float* __restrict__ W2) {
    const float* W = blockIdx.z ? W2 : W1;
    __half* Wt = blockIdx.z ? g_w2t : g_w1t;
    __shared__ float tile[32][33];
    int bx = blockIdx.x * 32, by = blockIdx.y * 32;
    int tx = threadIdx.x, ty = threadIdx.y;   // block (32, 8)
    #pragma unroll
    for (int i = 0; i < 32; i += 8)
        tile[ty + i][tx] = W[(by + ty + i) * DHID + bx + tx];
    __syncthreads();
    #pragma unroll
    for (int i = 0; i < 32; i += 8)
        Wt[(bx + ty + i) * KDIM + by + tx] = __float2half(tile[tx][ty + i]);
}

// ========================= CSR build =========================
__global__ void zero_deg_kernel() {
    int i = blockIdx.x * blockDim.x + threadIdx.x;
    if (i < N_NODES) g_deg[i] = 0;
}

__global__ void count_kernel(const int* __restrict__ ei) {
    int i = blockIdx.x * blockDim.x + threadIdx.x;
    if (i >= TOT_EDGES) return;
    int d = (i < N_EDGES) ? ei[N_EDGES + i] : (i - N_EDGES);
    atomicAdd(&g_deg[d], 1);
}

__global__ void block_reduce_kernel() {
    __shared__ int sh[256];
    int t = threadIdx.x;
    int i = blockIdx.x * 256 + t;
    sh[t] = (i < N_NODES) ? g_deg[i] : 0;
    __syncthreads();
    for (int o = 128; o > 0; o >>= 1) {
        if (t < o) sh[t] += sh[t + o];
        __syncthreads();
    }
    if (t == 0) g_blocksums[blockIdx.x] = sh[0];
}

__global__ void scan_blocks_kernel() {
    __shared__ int sh[256];
    int t = threadIdx.x;
    int v = (t < NBLK) ? g_blocksums[t] : 0;
    sh[t] = v;
    __syncthreads();
    for (int o = 1; o < 256; o <<= 1) {
        int x = (t >= o) ? sh[t - o] : 0;
        __syncthreads();
        sh[t] += x;
        __syncthreads();
    }
    if (t < NBLK) g_blocksums[t] = sh[t] - v;
}

__global__ void scatter_rowptr_kernel() {
    __shared__ int sh[256];
    int t = threadIdx.x;
    int i = blockIdx.x * 256 + t;
    int v = (i < N_NODES) ? g_deg[i] : 0;
    sh[t] = v;
    __syncthreads();
    for (int o = 1; o < 256; o <<= 1) {
        int x = (t >= o) ? sh[t - o] : 0;
        __syncthreads();
        sh[t] += x;
        __syncthreads();
    }
    int off = g_blocksums[blockIdx.x];
    if (i < N_NODES) {
        int r = off + sh[t] - v;
        g_rowptr[i] = r;
        g_cursor[i] = r;
        if (i == N_NODES - 1) g_rowptr[N_NODES] = TOT_EDGES;
    }
}

__global__ void fill_kernel(const int* __restrict__ ei) {
    int i = blockIdx.x * blockDim.x + threadIdx.x;
    if (i >= TOT_EDGES) return;
    int s, d;
    if (i < N_EDGES) { s = ei[i]; d = ei[N_EDGES + i]; }
    else             { s = d = i - N_EDGES; }
    int pos = atomicAdd(&g_cursor[d], 1);
    g_csr_src[pos] = s;
}

// ========================= fp16 GEMM + fused attn + fp16 store ===============
// layer 0: A = x (fp32, converted in the loader). layer 1: A = g_act (half).
#define BM 128
#define BN 128
#define BK 32
#define STRH 40

__global__ __launch_bounds__(256) void gemm_f16_kernel(
    int layer, const float* __restrict__ x32,
    const float* __restrict__ att_src, const float* __restrict__ att_dst)
{
    const __half* A  = (const __half*)g_act;     // layer 1 only
    const __half* Bt = layer ? (const __half*)g_w2t : (const __half*)g_w1t;

    __shared__ __half As[2][BM][STRH];
    __shared__ __half Bs[2][BN][STRH];
    float* s_attn = (float*)As;

    int bm = blockIdx.x * BM;
    int bn = blockIdx.y * BN;
    int tid  = threadIdx.x;
    int warp = tid >> 5;
    int lane = tid & 31;
    int wm = (warp & 1) * 64;
    int wn = (warp >> 1) * 32;
    int lr = lane >> 2;
    int lc = lane & 3;
    int lg = lane >> 3;     // ldmatrix group 0..3
    int rl = lane & 7;      // row within group

    float c[4][4][4];
    #pragma unroll
    for (int mt = 0; mt < 4; mt++)
        #pragma unroll
        for (int nt = 0; nt < 4; nt++)
            #pragma unroll
            for (int f = 0; f < 4; f++) c[mt][nt][f] = 0.f;

    auto load_B = [&](int st, int k0) {
        #pragma unroll
        for (int i = 0; i < 2; i++) {
            int idx = tid + i * 256;
            int r = idx >> 2;
            int cg = (idx & 3) * 8;
            uint32_t dst = (uint32_t)__cvta_generic_to_shared(&Bs[st][r][cg]);
            cp_async16(dst, &Bt[(long)(bn + r) * KDIM + k0 + cg], 16);
        }
    };
    auto load_A_h = [&](int st, int k0) {
        #pragma unroll
        for (int i = 0; i < 2; i++) {
            int idx = tid + i * 256;
            int r = idx >> 2;
            int cg = (idx & 3) * 8;
            int gr = bm + r;
            int valid = (gr < N_NODES);
            int src_row = valid ? gr : 0;
            uint32_t dst = (uint32_t)__cvta_generic_to_shared(&As[st][r][cg]);
            cp_async16(dst, &A[(long)src_row * KDIM + k0 + cg], valid ? 16 : 0);
        }
    };
    float4 areg[4];
    auto ldg_A_f = [&](int k0) {
        #pragma unroll
        for (int i = 0; i < 4; i++) {
            int idx = tid + i * 256;
            int r = idx >> 3;
            int cg = (idx & 7) * 4;
            int gr = bm + r;
            if (gr < N_NODES)
                areg[i] = *(const float4*)&x32[(long)gr * KDIM + k0 + cg];
            else
                areg[i] = make_float4(0.f, 0.f, 0.f, 0.f);
        }
    };
    auto sts_A_f = [&](int st) {
        #pragma unroll
        for (int i = 0; i < 4; i++) {
            int idx = tid + i * 256;
            int r = idx >> 3;
            int cg = (idx & 7) * 4;
            __half2 h01 = __floats2half2_rn(areg[i].x, areg[i].y);
            __half2 h23 = __floats2half2_rn(areg[i].z, areg[i].w);
            *(uint2*)&As[st][r][cg] = make_uint2(*(uint32_t*)&h01, *(uint32_t*)&h23);
        }
    };

    if (layer) {
        load_A_h(0, 0);
    } else {
        ldg_A_f(0);
        sts_A_f(0);
    }
    load_B(0, 0);
    asm volatile("cp.async.commit_group;");

    const int NITER = KDIM / BK;   // 8
    #pragma unroll 1
    for (int it = 0; it < NITER; it++) {
        int nxt = (it + 1) & 1;
        if (it + 1 < NITER) {
            if (layer) load_A_h(nxt, (it + 1) * BK);
            else       ldg_A_f((it + 1) * BK);
            load_B(nxt, (it + 1) * BK);
            asm volatile("cp.async.commit_group;");
            asm volatile("cp.async.wait_group 1;");
        } else {
            asm volatile("cp.async.wait_group 0;");
        }
        __syncthreads();
        int st = it & 1;

        #pragma unroll
        for (int ks = 0; ks < 2; ks++) {
            int k = ks * 16;
            uint32_t af[4][4];
            #pragma unroll
            for (int mt = 0; mt < 4; mt++) {
                const __half* p = &As[st][wm + mt * 16 + ((lg & 1) << 3) + rl]
                                        [k + ((lg >> 1) << 3)];
                ldsm_x4(af[mt][0], af[mt][1], af[mt][2], af[mt][3], p);
            }
            uint32_t bf[4][2];
            #pragma unroll
            for (int p2 = 0; p2 < 2; p2++) {
                int ntb = p2 * 2 + (lg >> 1);
                const __half* p = &Bs[st][wn + ntb * 8 + rl][k + ((lg & 1) << 3)];
                ldsm_x4(bf[p2 * 2][0], bf[p2 * 2][1],
                        bf[p2 * 2 + 1][0], bf[p2 * 2 + 1][1], p);
            }
            #pragma unroll
            for (int mt = 0; mt < 4; mt++)
                #pragma unroll
                for (int nt = 0; nt < 4; nt++) {
                    asm volatile(
                        "mma.sync.aligned.m16n8k16.row.col.f32.f16.f16.f32 "
                        "{%0,%1,%2,%3}, {%4,%5,%6,%7}, {%8,%9}, {%0,%1,%2,%3};"
                        : "+f"(c[mt][nt][0]), "+f"(c[mt][nt][1]),
                          "+f"(c[mt][nt][2]), "+f"(c[mt][nt][3])
                        : "r"(af[mt][0]), "r"(af[mt][1]), "r"(af[mt][2]), "r"(af[mt][3]),
                          "r"(bf[nt][0]), "r"(bf[nt][1]));
                }
        }
        if (!layer && it + 1 < NITER) sts_A_f(nxt);
        __syncthreads();
    }

    // ---- store C as fp16 ----
    #pragma unroll
    for (int mt = 0; mt < 4; mt++) {
        int row0 = bm + wm + mt * 16 + lr;
        #pragma unroll
        for (int nt = 0; nt < 4; nt++) {
            int col = bn + wn + nt * 8 + 2 * lc;
            if (row0 < N_NODES)
                *(__half2*)&g_h_half[(long)row0 * DHID + col] =
                    __floats2half2_rn(c[mt][nt][0], c[mt][nt][1]);
            if (row0 + 8 < N_NODES)
                *(__half2*)&g_h_half[(long)(row0 + 8) * DHID + col] =
                    __floats2half2_rn(c[mt][nt][2], c[mt][nt][3]);
        }
    }

    // ---- fused attention scores (block owns heads 2*by, 2*by+1) ----
    int head_l = wn >> 6;
    int slot   = (wn >> 5) & 1;
    float attS[4][2], attD[4][2];
    #pragma unroll
    for (int nt = 0; nt < 4; nt++)
        #pragma unroll
        for (int j = 0; j < 2; j++) {
            int col = bn + wn + nt * 8 + 2 * lc + j;
            attS[nt][j] = att_src[col];
            attD[nt][j] = att_dst[col];
        }
    __syncthreads();
    #pragma unroll
    for (int mt = 0; mt < 4; mt++) {
        float s0 = 0.f, d0 = 0.f, s1 = 0.f, d1 = 0.f;
        #pragma unroll
        for (int nt = 0; nt < 4; nt++) {
            s0 += c[mt][nt][0] * attS[nt][0] + c[mt][nt][1] * attS[nt][1];
            d0 += c[mt][nt][0] * attD[nt][0] + c[mt][nt][1] * attD[nt][1];
            s1 += c[mt][nt][2] * attS[nt][0] + c[mt][nt][3] * attS[nt][1];
            d1 += c[mt][nt][2] * attD[nt][0] + c[mt][nt][3] * attD[nt][1];
        }
        #pragma unroll
        for (int o = 1; o < 4; o <<= 1) {
            s0 += __shfl_xor_sync(0xFFFFFFFFu, s0, o);
            d0 += __shfl_xor_sync(0xFFFFFFFFu, d0, o);
            s1 += __shfl_xor_sync(0xFFFFFFFFu, s1, o);
            d1 += __shfl_xor_sync(0xFFFFFFFFu, d1, o);
        }
        if (lc == 0) {
            int r0 = wm + mt * 16 + lr;
            s_attn[((0 * 2 + head_l) * 2 + slot) * BM + r0]     = s0;
            s_attn[((1 * 2 + head_l) * 2 + slot) * BM + r0]     = d0;
            s_attn[((0 * 2 + head_l) * 2 + slot) * BM + r0 + 8] = s1;
            s_attn[((1 * 2 + head_l) * 2 + slot) * BM + r0 + 8] = d1;
        }
    }
    __syncthreads();
    {
        int row = tid & 127;
        int hl  = tid >> 7;
        int node = bm + row;
        if (node < N_NODES) {
            int hg = blockIdx.y * 2 + hl;
            g_asrc[node * 4 + hg] = s_attn[((0 * 2 + hl) * 2 + 0) * BM + row]
                                  + s_attn[((0 * 2 + hl) * 2 + 1) * BM + row];
            g_adst[node * 4 + hg] = s_attn[((1 * 2 + hl) * 2 + 0) * BM + row]
                                  + s_attn[((1 * 2 + hl) * 2 + 1) * BM + row];
        }
    }
}

// ========================= fused aggregate (warp per node, single pass) ======
// out = (Σ_e exp(lrelu(a_src[e]+a_dst)) * h[src_e]) / (Σ_e exp(...) + eps)
// Every lane walks all edges, so den accumulates identically per-lane for its
// head -- no second pass and no reduction needed.
__device__ __forceinline__ void fma8(float* acc, float alpha, uint4 raw) {
    float2 f0 = __half22float2(*(__half2*)&raw.x);
    float2 f1 = __half22float2(*(__half2*)&raw.y);
    float2 f2 = __half22float2(*(__half2*)&raw.z);
    float2 f3 = __half22float2(*(__half2*)&raw.w);
    acc[0] += alpha * f0.x; acc[1] += alpha * f0.y;
    acc[2] += alpha * f1.x; acc[3] += alpha * f1.y;
    acc[4] += alpha * f2.x; acc[5] += alpha * f2.y;
    acc[6] += alpha * f3.x; acc[7] += alpha * f3.y;
}

__global__ __launch_bounds__(256) void gat_aggregate_kernel(
    const float* __restrict__ bias, float* __restrict__ dst_ext, int to_act)
{
    int n    = (blockIdx.x * blockDim.x + threadIdx.x) >> 5;
    int lane = threadIdx.x & 31;
    if (n >= N_NODES) return;
    int beg = g_rowptr[n];
    int end = g_rowptr[n + 1];
    int head = lane >> 3;
    float adst_h = g_adst[n * 4 + head];

    float acc[8] = {0.f, 0.f, 0.f, 0.f, 0.f, 0.f, 0.f, 0.f};
    float den = 0.f;
    int e = beg;
    for (; e + 4 <= end; e += 4) {
        int i0 = g_csr_src[e];
        int i1 = g_csr_src[e + 1];
        int i2 = g_csr_src[e + 2];
        int i3 = g_csr_src[e + 3];
        float a0 = __ldg(&g_asrc[i0 * 4 + head]);
        float a1 = __ldg(&g_asrc[i1 * 4 + head]);
        float a2 = __ldg(&g_asrc[i2 * 4 + head]);
        float a3 = __ldg(&g_asrc[i3 * 4 + head]);
        uint4 r0 = *(const uint4*)&g_h_half[(long)i0 * DHID + lane * 8];
        uint4 r1 = *(const uint4*)&g_h_half[(long)i1 * DHID + lane * 8];
        uint4 r2 = *(const uint4*)&g_h_half[(long)i2 * DHID + lane * 8];
        uint4 r3 = *(const uint4*)&g_h_half[(long)i3 * DHID + lane * 8];
        float e0 = a0 + adst_h; e0 = (e0 > 0.f) ? e0 : 0.2f * e0;
        float e1 = a1 + adst_h; e1 = (e1 > 0.f) ? e1 : 0.2f * e1;
        float e2 = a2 + adst_h; e2 = (e2 > 0.f) ? e2 : 0.2f * e2;
        float e3 = a3 + adst_h; e3 = (e3 > 0.f) ? e3 : 0.2f * e3;
        float x0 = __expf(e0), x1 = __expf(e1), x2 = __expf(e2), x3 = __expf(e3);
        den += x0 + x1 + x2 + x3;
        fma8(acc, x0, r0);
        fma8(acc, x1, r1);
        fma8(acc, x2, r2);
        fma8(acc, x3, r3);
    }
    for (; e < end; e++) {
        int i0 = g_csr_src[e];
        float a0 = __ldg(&g_asrc[i0 * 4 + head]);
        uint4 r0 = *(const uint4*)&g_h_half[(long)i0 * DHID + lane * 8];
        float e0 = a0 + adst_h; e0 = (e0 > 0.f) ? e0 : 0.2f * e0;
        float x0 = __expf(e0);
        den += x0;
        fma8(acc, x0, r0);
    }

    float inv = 1.f / (den + 1e-16f);

    // epilogue: normalize + bias + ELU + store
    float4 b0 = ((const float4*)bias)[lane * 2];
    float4 b1 = ((const float4*)bias)[lane * 2 + 1];
    float bb[8] = {b0.x, b0.y, b0.z, b0.w, b1.x, b1.y, b1.z, b1.w};
    #pragma unroll
    for (int i = 0; i < 8; i++) {
        float v = acc[i] * inv + bb[i];
        acc[i] = (v > 0.f) ? v : expm1f(v);
    }
    if (to_act) {
        __half2 h0 = __floats2half2_rn(acc[0], acc[1]);
        __half2 h1 = __floats2half2_rn(acc[2], acc[3]);
        __half2 h2 = __floats2half2_rn(acc[4], acc[5]);
        __half2 h3 = __floats2half2_rn(acc[6], acc[7]);
        uint4 packed = make_uint4(*(uint32_t*)&h0, *(uint32_t*)&h1,
                                  *(uint32_t*)&h2, *(uint32_t*)&h3);
        *(uint4*)&g_act[(long)n * DHID + lane * 8] = packed;
    } else {
        float* op = &dst_ext[(long)n * DHID + lane * 8];
        *(float4*)op       = make_float4(acc[0], acc[1], acc[2], acc[3]);
        *(float4*)(op + 4) = make_float4(acc[4], acc[5], acc[6], acc[7]);
    }
}

// ========================= launch =========================
extern "C" void kernel_launch(void* const* d_in, const int* in_sizes, int n_in,
                              void* d_out, int out_size)
{
    const float* x   = (const float*)d_in[0];
    const int*   ei  = (const int*)  d_in[1];
    const float* W1  = (const float*)d_in[2];
    const float* as1 = (const float*)d_in[3];
    const float* ad1 = (const float*)d_in[4];
    const float* b1  = (const float*)d_in[5];
    const float* W2  = (const float*)d_in[6];
    const float* as2 = (const float*)d_in[7];
    const float* ad2 = (const float*)d_in[8];
    const float* b2  = (const float*)d_in[9];
    float* out = (float*)d_out;

    cudaStream_t s0 = 0;           // legacy default (captured stream)
    cudaStream_t s2 = g_gs.s2;

    dim3 gemm_grid((N_NODES + BM - 1) / BM, DHID / BN);
    int edge_blocks = (TOT_EDGES + 255) / 256;
    int agg_blocks  = (N_NODES + 7) / 8;
    dim3 wgrid(8, 8, 2), wblk(32, 8);

    // fork point
    cudaEventRecord(g_gs.ev0, s0);
    cudaStreamWaitEvent(s2, g_gs.ev0, 0);

    // ---- s0: CSR build (starts immediately) ----
    zero_deg_kernel<<<NBLK, 256, 0, s0>>>();
    count_kernel<<<edge_blocks, 256, 0, s0>>>(ei);
    block_reduce_kernel<<<NBLK, 256, 0, s0>>>();
    scan_blocks_kernel<<<1, 256, 0, s0>>>();
    scatter_rowptr_kernel<<<NBLK, 256, 0, s0>>>();
    fill_kernel<<<edge_blocks, 256, 0, s0>>>(ei);

    // ---- s2: weights + layer-1 GEMM (reads fp32 x directly) ----
    convert_w_kernel<<<wgrid, wblk, 0, s2>>>(W1, W2);
    gemm_f16_kernel<<<gemm_grid, 256, 0, s2>>>(0, x, as1, ad1);
    cudaEventRecord(g_gs.evG1, s2);

    // ---- s0: join, then the serial tail ----
    cudaStreamWaitEvent(s0, g_gs.evG1, 0);
    gat_aggregate_kernel<<<agg_blocks, 256, 0, s0>>>(b1, nullptr, 1);
    gemm_f16_kernel<<<gemm_grid, 256, 0, s0>>>(1, nullptr, as2, ad2);
    gat_aggregate_kernel<<<agg_blocks, 256, 0, s0>>>(b2, out, 0);
}